// round 1
// baseline (speedup 1.0000x reference)
#include <cuda_runtime.h>
#include <math.h>
#include <float.h>

// ---------------- problem constants ----------------
#define DIMX 2048
#define NSEQ 2048
#define BATCH 2
#define HEADS 16
#define DHEAD 64
#define ROWS (BATCH*NSEQ)          // 4096
#define AINNER 1024                // HEADS*DHEAD
#define FFINNER 8192
#define FUSEDC 17536               // 1024 + 64 + 64 + 2*8192
#define I0 1024
#define I1 1088
#define I2 1152
#define RLORA 8

// ---------------- scratch (device globals; no allocation allowed) --------
__device__ float g_XN[8388608];          // [4096,2048]
__device__ float g_F[71827456];          // [4096,17536]
__device__ float g_XA[98304];            // [4096,24]  (q:0-7, k:8-15, v:16-23)
__device__ float g_Q[4194304];           // [4096,1024] roped+scaled
__device__ float g_K[262144];            // [4096,64]   roped
__device__ float g_V[262144];            // [4096,64]
__device__ float g_OATTN[4194304];       // [4096,1024]
__device__ float g_OA[32768];            // [4096,8]
__device__ float g_H[33554432];          // [4096,8192]

// ---------------- layernorm ----------------
__global__ void ln_kernel(const float* __restrict__ x, const float* __restrict__ gamma,
                          float* __restrict__ xn) {
    int row = blockIdx.x;
    const float* xr = x + (size_t)row * DIMX;
    float s = 0.f, s2 = 0.f;
    for (int i = threadIdx.x; i < DIMX; i += 256) {
        float v = xr[i]; s += v; s2 += v * v;
    }
    // warp reduce
    for (int o = 16; o > 0; o >>= 1) {
        s  += __shfl_xor_sync(0xffffffff, s,  o);
        s2 += __shfl_xor_sync(0xffffffff, s2, o);
    }
    __shared__ float sh[16];
    int wid = threadIdx.x >> 5, lane = threadIdx.x & 31;
    if (lane == 0) { sh[wid] = s; sh[8 + wid] = s2; }
    __syncthreads();
    if (threadIdx.x == 0) {
        float S = 0.f, S2 = 0.f;
        for (int w = 0; w < 8; w++) { S += sh[w]; S2 += sh[8 + w]; }
        sh[0] = S; sh[8] = S2;
    }
    __syncthreads();
    float mu = sh[0] * (1.f / DIMX);
    float var = sh[8] * (1.f / DIMX) - mu * mu;
    float inv = rsqrtf(var + 1e-5f);
    float* o = xn + (size_t)row * DIMX;
    for (int i = threadIdx.x; i < DIMX; i += 256)
        o[i] = (xr[i] - mu) * inv * gamma[i];
}

// ---------------- generic SGEMM: C[M,N] = A[M,K] @ B[K,N] (+C if accum) ---
// 128x128 block tile, BK=8, 256 threads, 8x8 microtile. M%128==0, N%128==0, K%8==0.
#define BM 128
#define BN 128
#define BK 8
#define TM 8
#define TN 8
__global__ __launch_bounds__(256) void sgemm(const float* __restrict__ A,
                                             const float* __restrict__ B,
                                             float* __restrict__ C,
                                             int M, int N, int K, int accum) {
    __shared__ float As[BK][BM];
    __shared__ float Bs[BK][BN];
    int t = threadIdx.x;
    int tx = t & 15, ty = t >> 4;
    int aRow = t >> 1;
    int aCol4 = (t & 1) * 4;
    int bRow = t >> 5;
    int bCol4 = (t & 31) * 4;
    const float* Ablk = A + (size_t)blockIdx.y * BM * K;
    const float* Bblk = B + (size_t)blockIdx.x * BN;
    float acc[TM][TN];
#pragma unroll
    for (int i = 0; i < TM; i++)
#pragma unroll
        for (int j = 0; j < TN; j++) acc[i][j] = 0.f;

    for (int k0 = 0; k0 < K; k0 += BK) {
        float4 av = *(const float4*)(Ablk + (size_t)aRow * K + k0 + aCol4);
        As[aCol4 + 0][aRow] = av.x;
        As[aCol4 + 1][aRow] = av.y;
        As[aCol4 + 2][aRow] = av.z;
        As[aCol4 + 3][aRow] = av.w;
        *(float4*)&Bs[bRow][bCol4] = *(const float4*)(Bblk + (size_t)(k0 + bRow) * N + bCol4);
        __syncthreads();
#pragma unroll
        for (int kk = 0; kk < BK; kk++) {
            float4 a0 = *(const float4*)&As[kk][ty * TM];
            float4 a1 = *(const float4*)&As[kk][ty * TM + 4];
            float4 b0 = *(const float4*)&Bs[kk][tx * TN];
            float4 b1 = *(const float4*)&Bs[kk][tx * TN + 4];
            float af[TM] = {a0.x, a0.y, a0.z, a0.w, a1.x, a1.y, a1.z, a1.w};
            float bf[TN] = {b0.x, b0.y, b0.z, b0.w, b1.x, b1.y, b1.z, b1.w};
#pragma unroll
            for (int i = 0; i < TM; i++)
#pragma unroll
                for (int j = 0; j < TN; j++) acc[i][j] += af[i] * bf[j];
        }
        __syncthreads();
    }
    float* Cblk = C + (size_t)(blockIdx.y * BM + ty * TM) * N + blockIdx.x * BN + tx * TN;
#pragma unroll
    for (int i = 0; i < TM; i++) {
#pragma unroll
        for (int j = 0; j < TN; j += 4) {
            float4* p = (float4*)(Cblk + (size_t)i * N + j);
            float4 r = make_float4(acc[i][j], acc[i][j + 1], acc[i][j + 2], acc[i][j + 3]);
            if (accum) {
                float4 c = *p;
                r.x += c.x; r.y += c.y; r.z += c.z; r.w += c.w;
            }
            *p = r;
        }
    }
}

// ---------------- LoRA first stage: XA[row,24] = xn_row @ [a_q|a_k|a_v] ---
__global__ void lora_xa_kernel(const float* __restrict__ xn,
                               const float* __restrict__ aq,
                               const float* __restrict__ ak,
                               const float* __restrict__ av,
                               float* __restrict__ xa) {
    int row = blockIdx.x;
    const float* xr = xn + (size_t)row * DIMX;
    float acc[24];
#pragma unroll
    for (int m = 0; m < 24; m++) acc[m] = 0.f;
    for (int i = threadIdx.x; i < DIMX; i += 256) {
        float v = xr[i];
#pragma unroll
        for (int r = 0; r < 8; r++) {
            acc[r]      += v * aq[i * 8 + r];
            acc[8 + r]  += v * ak[i * 8 + r];
            acc[16 + r] += v * av[i * 8 + r];
        }
    }
    __shared__ float sh[8][24];
    int wid = threadIdx.x >> 5, lane = threadIdx.x & 31;
#pragma unroll
    for (int m = 0; m < 24; m++)
        for (int o = 16; o > 0; o >>= 1)
            acc[m] += __shfl_xor_sync(0xffffffff, acc[m], o);
    if (lane == 0)
#pragma unroll
        for (int m = 0; m < 24; m++) sh[wid][m] = acc[m];
    __syncthreads();
    if (threadIdx.x < 24) {
        float s = 0.f;
        for (int w = 0; w < 8; w++) s += sh[w][threadIdx.x];
        xa[row * 24 + threadIdx.x] = s;
    }
}

// ---------------- qkv prep: add LoRA, scale q, RoPE q & k, write V -------
__global__ void qkv_prep(const float* __restrict__ F, const float* __restrict__ XA,
                         const float* __restrict__ bq, const float* __restrict__ bk,
                         const float* __restrict__ bv,
                         float* __restrict__ Q, float* __restrict__ Kv, float* __restrict__ V) {
    int row = blockIdx.x;
    int n = row % NSEQ;
    __shared__ float qs[AINNER];
    __shared__ float ks[DHEAD];
    const float* Fr = F + (size_t)row * FUSEDC;
    const float* xa = XA + row * 24;
    float lq[8], lk[8], lv[8];
#pragma unroll
    for (int r = 0; r < 8; r++) { lq[r] = xa[r]; lk[r] = xa[8 + r]; lv[r] = xa[16 + r]; }

    for (int c = threadIdx.x; c < AINNER; c += 256) {
        float v = Fr[c];
#pragma unroll
        for (int r = 0; r < 8; r++) v += lq[r] * bq[r * AINNER + c];
        qs[c] = v;
    }
    if (threadIdx.x < DHEAD) {
        int c = threadIdx.x;
        float v = Fr[I0 + c];
#pragma unroll
        for (int r = 0; r < 8; r++) v += lk[r] * bk[r * DHEAD + c];
        ks[c] = v;
        float vv = Fr[I1 + c];
#pragma unroll
        for (int r = 0; r < 8; r++) vv += lv[r] * bv[r * DHEAD + c];
        V[(size_t)row * DHEAD + c] = vv;
    }
    __syncthreads();

    const float ln10k_inv32 = 9.2103403719761836f / 32.f; // ln(10000)/32
    const float scale = 0.125f; // 64^-0.5
    for (int c = threadIdx.x; c < AINNER; c += 256) {
        int h = c >> 6, d = c & 63;
        int fi = d & 31;
        float freq = (float)n * __expf(-(float)fi * ln10k_inv32);
        float cs = cosf(freq), sn = sinf(freq);
        float me = qs[c];
        float partner = (d < 32) ? -qs[h * 64 + d + 32] : qs[h * 64 + d - 32];
        Q[(size_t)row * AINNER + c] = (me * cs + partner * sn) * scale;
    }
    if (threadIdx.x < DHEAD) {
        int d = threadIdx.x;
        int fi = d & 31;
        float freq = (float)n * __expf(-(float)fi * ln10k_inv32);
        float cs = cosf(freq), sn = sinf(freq);
        float me = ks[d];
        float partner = (d < 32) ? -ks[d + 32] : ks[d - 32];
        Kv[(size_t)row * DHEAD + d] = me * cs + partner * sn;
    }
}

// ---------------- causal flash attention (multi-query: K,V shared by heads)
// one block per (b,n); 16 warps = 16 heads; 32-key chunks in shared.
__global__ __launch_bounds__(512) void attn_kernel(const float* __restrict__ Q,
                                                   const float* __restrict__ Kk,
                                                   const float* __restrict__ V,
                                                   float* __restrict__ O) {
    int row = blockIdx.x;          // b*NSEQ + n
    int n = row % NSEQ;
    int b = row / NSEQ;
    int wid = threadIdx.x >> 5;    // head
    int lane = threadIdx.x & 31;

    __shared__ float Qs[HEADS][DHEAD];
    __shared__ float Ks[32][65];
    __shared__ float Vs[32][65];
    __shared__ float Ps[HEADS][32];

    for (int idx = threadIdx.x; idx < HEADS * DHEAD; idx += 512)
        Qs[idx >> 6][idx & 63] = Q[(size_t)row * AINNER + idx];

    const float* Kb = Kk + (size_t)b * NSEQ * DHEAD;
    const float* Vb = V + (size_t)b * NSEQ * DHEAD;

    float m = -FLT_MAX, l = 0.f, acc0 = 0.f, acc1 = 0.f;

    for (int j0 = 0; j0 <= n; j0 += 32) {
        int cnt = min(32, n + 1 - j0);
        __syncthreads();
        for (int idx = threadIdx.x; idx < 32 * 64; idx += 512) {
            int jj = idx >> 6, d = idx & 63;
            float kv = 0.f, vv = 0.f;
            if (jj < cnt) {
                kv = Kb[(size_t)(j0 + jj) * DHEAD + d];
                vv = Vb[(size_t)(j0 + jj) * DHEAD + d];
            }
            Ks[jj][d] = kv;
            Vs[jj][d] = vv;
        }
        __syncthreads();

        float s = -FLT_MAX;
        if (lane < cnt) {
            s = 0.f;
#pragma unroll
            for (int d = 0; d < 64; d++) s += Qs[wid][d] * Ks[lane][d];
        }
        float smax = s;
        for (int o = 16; o > 0; o >>= 1) smax = fmaxf(smax, __shfl_xor_sync(0xffffffff, smax, o));
        float mnew = fmaxf(m, smax);
        float p = (lane < cnt) ? __expf(s - mnew) : 0.f;
        float ps = p;
        for (int o = 16; o > 0; o >>= 1) ps += __shfl_xor_sync(0xffffffff, ps, o);
        float corr = __expf(m - mnew);
        l = l * corr + ps;
        acc0 *= corr; acc1 *= corr;
        Ps[wid][lane] = p;
        __syncwarp();
#pragma unroll
        for (int j = 0; j < 32; j++) {
            float pj = Ps[wid][j];
            acc0 += pj * Vs[j][lane];
            acc1 += pj * Vs[j][32 + lane];
        }
        m = mnew;
    }
    float invl = 1.f / l;
    O[(size_t)row * AINNER + wid * 64 + lane]      = acc0 * invl;
    O[(size_t)row * AINNER + wid * 64 + 32 + lane] = acc1 * invl;
}

// ---------------- OA[row,8] = OATTN_row @ a_o ----------------
__global__ void lora_oa_kernel(const float* __restrict__ oattn,
                               const float* __restrict__ ao,
                               float* __restrict__ oa) {
    int row = blockIdx.x;
    const float* xr = oattn + (size_t)row * AINNER;
    float acc[8];
#pragma unroll
    for (int r = 0; r < 8; r++) acc[r] = 0.f;
    for (int i = threadIdx.x; i < AINNER; i += 256) {
        float v = xr[i];
#pragma unroll
        for (int r = 0; r < 8; r++) acc[r] += v * ao[i * 8 + r];
    }
    __shared__ float sh[8][8];
    int wid = threadIdx.x >> 5, lane = threadIdx.x & 31;
#pragma unroll
    for (int r = 0; r < 8; r++)
        for (int o = 16; o > 0; o >>= 1)
            acc[r] += __shfl_xor_sync(0xffffffff, acc[r], o);
    if (lane == 0)
#pragma unroll
        for (int r = 0; r < 8; r++) sh[wid][r] = acc[r];
    __syncthreads();
    if (threadIdx.x < 8) {
        float s = 0.f;
        for (int w = 0; w < 8; w++) s += sh[w][threadIdx.x];
        oa[row * 8 + threadIdx.x] = s;
    }
}

// ---------------- H = silu(gate) * ff_x ----------------
__global__ void hcombine(const float* __restrict__ F, float* __restrict__ H) {
    size_t idx = (size_t)blockIdx.x * blockDim.x + threadIdx.x;
    size_t row = idx / FFINNER;
    int c = (int)(idx % FFINNER);
    const float* Fr = F + row * FUSEDC;
    float g = Fr[I2 + FFINNER + c];
    float xx = Fr[I2 + c];
    H[idx] = xx * g / (1.f + __expf(-g));
}

// ---------------- out += OA @ b_o ----------------
__global__ void lora_o_add(const float* __restrict__ oa, const float* __restrict__ bo,
                           float* __restrict__ out) {
    int row = blockIdx.y;
    int c = blockIdx.x * 256 + threadIdx.x;
    float s = 0.f;
#pragma unroll
    for (int r = 0; r < 8; r++) s += oa[row * 8 + r] * bo[r * DIMX + c];
    out[(size_t)row * DIMX + c] += s;
}

// ---------------- launch ----------------
extern "C" void kernel_launch(void* const* d_in, const int* in_sizes, int n_in,
                              void* d_out, int out_size) {
    const float* x          = (const float*)d_in[0];
    const float* gamma      = (const float*)d_in[1];
    const float* w_fused    = (const float*)d_in[2];
    const float* w_attn_out = (const float*)d_in[3];
    const float* w_ff_out   = (const float*)d_in[4];
    const float* a_q        = (const float*)d_in[5];
    const float* b_q        = (const float*)d_in[6];
    const float* a_k        = (const float*)d_in[7];
    const float* b_k        = (const float*)d_in[8];
    const float* a_v        = (const float*)d_in[9];
    const float* b_v        = (const float*)d_in[10];
    const float* a_o        = (const float*)d_in[11];
    const float* b_o        = (const float*)d_in[12];
    float* out = (float*)d_out;

    float *XN, *F, *XA, *Q, *K, *V, *OATTN, *OA, *H;
    cudaGetSymbolAddress((void**)&XN, g_XN);
    cudaGetSymbolAddress((void**)&F, g_F);
    cudaGetSymbolAddress((void**)&XA, g_XA);
    cudaGetSymbolAddress((void**)&Q, g_Q);
    cudaGetSymbolAddress((void**)&K, g_K);
    cudaGetSymbolAddress((void**)&V, g_V);
    cudaGetSymbolAddress((void**)&OATTN, g_OATTN);
    cudaGetSymbolAddress((void**)&OA, g_OA);
    cudaGetSymbolAddress((void**)&H, g_H);

    ln_kernel<<<ROWS, 256>>>(x, gamma, XN);
    sgemm<<<dim3(FUSEDC / 128, ROWS / 128), 256>>>(XN, w_fused, F, ROWS, FUSEDC, DIMX, 0);
    lora_xa_kernel<<<ROWS, 256>>>(XN, a_q, a_k, a_v, XA);
    qkv_prep<<<ROWS, 256>>>(F, XA, b_q, b_k, b_v, Q, K, V);
    attn_kernel<<<ROWS, 512>>>(Q, K, V, OATTN);
    sgemm<<<dim3(DIMX / 128, ROWS / 128), 256>>>(OATTN, w_attn_out, out, ROWS, DIMX, AINNER, 0);
    lora_oa_kernel<<<ROWS, 256>>>(OATTN, a_o, OA);
    hcombine<<<(ROWS * (size_t)FFINNER) / 256, 256>>>(F, H);
    sgemm<<<dim3(DIMX / 128, ROWS / 128), 256>>>(H, w_ff_out, out, ROWS, DIMX, FFINNER, 1);
    lora_o_add<<<dim3(DIMX / 256, ROWS), 256>>>(OA, b_o, out);
}

// round 4
// speedup vs baseline: 2.6066x; 2.6066x over previous
#include <cuda_runtime.h>
#include <cuda_bf16.h>
#include <math.h>
#include <float.h>
#include <stdint.h>

// ---------------- problem constants ----------------
#define DIMX 2048
#define NSEQ 2048
#define BATCH 2
#define HEADS 16
#define DHEAD 64
#define ROWS (BATCH*NSEQ)          // 4096
#define AINNER 1024
#define FFINNER 8192
#define FUSEDC 17536               // 1024+64+64+2*8192
#define FPAD 17664                 // 138*128
#define I0 1024
#define I1 1088
#define I2 1152

// ---------------- scratch (device globals) --------
__device__ float g_XN[(size_t)ROWS*DIMX];
__device__ float g_WF[(size_t)DIMX*FPAD];        // rounded+padded w_fused
__device__ float g_F[(size_t)ROWS*FPAD];
__device__ float g_XA[ROWS*24];
__device__ float g_Q[(size_t)ROWS*AINNER];
__device__ float g_K[(size_t)ROWS*DHEAD];
__device__ float g_V[(size_t)ROWS*DHEAD];
__device__ float g_OATTN[(size_t)ROWS*AINNER];
__device__ float g_WAO[(size_t)AINNER*DIMX];
__device__ float g_H[(size_t)ROWS*FFINNER];
__device__ float g_WFF[(size_t)FFINNER*DIMX];
__device__ float g_OA[ROWS*8];

// ---------------- small helpers ----------------
__device__ __forceinline__ float tf32r(float x) {
    uint32_t u;
    asm("cvt.rna.tf32.f32 %0, %1;" : "=r"(u) : "f"(x));
    return __uint_as_float(u);
}
__device__ __forceinline__ uint32_t smem_u32(const void* p) {
    uint32_t a;
    asm("{ .reg .u64 t; cvta.to.shared.u64 t, %1; cvt.u32.u64 %0, t; }" : "=r"(a) : "l"(p));
    return a;
}
__device__ __forceinline__ void cp16(uint32_t saddr, const void* g) {
    asm volatile("cp.async.cg.shared.global [%0], [%1], 16;" :: "r"(saddr), "l"(g) : "memory");
}
__device__ __forceinline__ void mma_tf32(float* d, const uint32_t* a, const uint32_t* b) {
    asm volatile(
        "mma.sync.aligned.m16n8k8.row.col.f32.tf32.tf32.f32 "
        "{%0,%1,%2,%3}, {%4,%5,%6,%7}, {%8,%9}, {%0,%1,%2,%3};"
        : "+f"(d[0]), "+f"(d[1]), "+f"(d[2]), "+f"(d[3])
        : "r"(a[0]), "r"(a[1]), "r"(a[2]), "r"(a[3]), "r"(b[0]), "r"(b[1]));
}

// ================= TF32 GEMM =================
// C[M,N] = A[M,K] @ B[K,N] (+= if accum). All fp32 memory (pre-rounded to tf32).
// 128x128x16 CTA tile, 256 thr, 8 warps (4m x 2n), warp tile 32x64, 3-stage cp.async.
#define GSTAGES 3
#define AST 20            // A smem row stride (words), row=m (128 rows x 16 k)
#define BST 136           // B smem row stride (words), row=k (16 rows x 128 n)
#define AWORDS (128*AST)  // 2560
#define BWORDS (16*BST)   // 2176
#define STW (AWORDS+BWORDS)   // 4736 words per stage
#define GSMEM (GSTAGES*STW*4) // 56832 bytes

__global__ __launch_bounds__(256) void tf32_gemm(const float* __restrict__ A,
                                                 const float* __restrict__ B,
                                                 float* __restrict__ C,
                                                 int N, int K, int accum) {
    extern __shared__ float smem[];
    const int tid = threadIdx.x;
    const int wid = tid >> 5, lane = tid & 31;
    const int wm = (wid & 3) * 32, wn = (wid >> 2) * 64;
    const int m0 = blockIdx.x * 128, n0 = blockIdx.y * 128;
    const float* Ag = A + (size_t)m0 * K;
    const float* Bg = B + n0;
    const uint32_t sb = smem_u32(smem);

    const int arow = tid >> 2, ak4 = (tid & 3) * 4;
    const int brow = tid >> 5, bn4 = (tid & 31) * 4;
    const int NK = K >> 4;

    auto load_stage = [&](int kt, int s) {
        const uint32_t sa = sb + s * STW * 4;
        const uint32_t sB = sa + AWORDS * 4;
        const float* ag = Ag + kt * 16;
        const float* bg = Bg + (size_t)(kt * 16) * N;
#pragma unroll
        for (int i = 0; i < 2; i++) {
            int r = arow + i * 64;
            cp16(sa + (r * AST + ak4) * 4, ag + (size_t)r * K + ak4);
            int kr = brow + i * 8;
            cp16(sB + (kr * BST + bn4) * 4, bg + (size_t)kr * N + bn4);
        }
    };

    float acc[2][8][4];
#pragma unroll
    for (int mt = 0; mt < 2; mt++)
#pragma unroll
        for (int nt = 0; nt < 8; nt++)
#pragma unroll
            for (int i = 0; i < 4; i++) acc[mt][nt][i] = 0.f;

    load_stage(0, 0);
    asm volatile("cp.async.commit_group;" ::: "memory");
    load_stage(1, 1);
    asm volatile("cp.async.commit_group;" ::: "memory");

#pragma unroll 1
    for (int kt = 0; kt < NK; kt++) {
        asm volatile("cp.async.wait_group 1;" ::: "memory");
        __syncthreads();
        if (kt + 2 < NK) load_stage(kt + 2, (kt + 2) % GSTAGES);
        asm volatile("cp.async.commit_group;" ::: "memory");

        const int s = kt % GSTAGES;
        const float* As = smem + s * STW;
        const float* Bs = As + AWORDS;
#pragma unroll
        for (int c8 = 0; c8 < 2; c8++) {
            const int c = c8 * 8;
            uint32_t a[2][4], b[8][2];
            const int kk = c + (lane & 3);
#pragma unroll
            for (int mt = 0; mt < 2; mt++) {
                int r = wm + mt * 16 + (lane >> 2);
                a[mt][0] = __float_as_uint(As[r * AST + kk]);
                a[mt][1] = __float_as_uint(As[(r + 8) * AST + kk]);
                a[mt][2] = __float_as_uint(As[r * AST + kk + 4]);
                a[mt][3] = __float_as_uint(As[(r + 8) * AST + kk + 4]);
            }
#pragma unroll
            for (int nt = 0; nt < 8; nt++) {
                int n = wn + nt * 8 + (lane >> 2);
                b[nt][0] = __float_as_uint(Bs[kk * BST + n]);
                b[nt][1] = __float_as_uint(Bs[(kk + 4) * BST + n]);
            }
#pragma unroll
            for (int mt = 0; mt < 2; mt++)
#pragma unroll
                for (int nt = 0; nt < 8; nt++)
                    mma_tf32(acc[mt][nt], a[mt], b[nt]);
        }
    }

    // epilogue
    const int rbase = m0 + wm + (lane >> 2);
    const int cbase = n0 + wn + (lane & 3) * 2;
#pragma unroll
    for (int mt = 0; mt < 2; mt++) {
#pragma unroll
        for (int nt = 0; nt < 8; nt++) {
            int r = rbase + mt * 16;
            int cc = cbase + nt * 8;
            float2* p0 = (float2*)(C + (size_t)r * N + cc);
            float2* p1 = (float2*)(C + (size_t)(r + 8) * N + cc);
            float2 v0 = make_float2(acc[mt][nt][0], acc[mt][nt][1]);
            float2 v1 = make_float2(acc[mt][nt][2], acc[mt][nt][3]);
            if (accum) {
                float2 o0 = *p0, o1 = *p1;
                v0.x += o0.x; v0.y += o0.y; v1.x += o1.x; v1.y += o1.y;
            }
            *p0 = v0; *p1 = v1;
        }
    }
}

// ---------------- weight rounding (+ column pad) ----------------
__global__ void round_pad(const float* __restrict__ in, float* __restrict__ out,
                          int Nin4, int Nout4) {
    int row = blockIdx.y;
    int c4 = blockIdx.x * 256 + threadIdx.x;
    if (c4 >= Nout4) return;
    float4 v = make_float4(0.f, 0.f, 0.f, 0.f);
    if (c4 < Nin4) {
        v = ((const float4*)(in + (size_t)row * Nin4 * 4))[c4];
        v.x = tf32r(v.x); v.y = tf32r(v.y); v.z = tf32r(v.z); v.w = tf32r(v.w);
    }
    ((float4*)(out + (size_t)row * Nout4 * 4))[c4] = v;
}

// ---------------- layernorm (tf32-rounded out) ----------------
__global__ void ln_kernel(const float* __restrict__ x, const float* __restrict__ gamma,
                          float* __restrict__ xn) {
    int row = blockIdx.x;
    const float* xr = x + (size_t)row * DIMX;
    float s = 0.f, s2 = 0.f;
    for (int i = threadIdx.x; i < DIMX; i += 256) { float v = xr[i]; s += v; s2 += v * v; }
    for (int o = 16; o > 0; o >>= 1) {
        s  += __shfl_xor_sync(0xffffffff, s,  o);
        s2 += __shfl_xor_sync(0xffffffff, s2, o);
    }
    __shared__ float sh[16];
    int wid = threadIdx.x >> 5, lane = threadIdx.x & 31;
    if (lane == 0) { sh[wid] = s; sh[8 + wid] = s2; }
    __syncthreads();
    if (threadIdx.x == 0) {
        float S = 0.f, S2 = 0.f;
        for (int w = 0; w < 8; w++) { S += sh[w]; S2 += sh[8 + w]; }
        sh[0] = S; sh[8] = S2;
    }
    __syncthreads();
    float mu = sh[0] * (1.f / DIMX);
    float var = sh[8] * (1.f / DIMX) - mu * mu;
    float inv = rsqrtf(var + 1e-5f);
    float* o = xn + (size_t)row * DIMX;
    for (int i = threadIdx.x; i < DIMX; i += 256)
        o[i] = tf32r((xr[i] - mu) * inv * gamma[i]);
}

// ---------------- LoRA first stage ----------------
__global__ void lora_xa_kernel(const float* __restrict__ xn,
                               const float* __restrict__ aq,
                               const float* __restrict__ ak,
                               const float* __restrict__ av,
                               float* __restrict__ xa) {
    int row = blockIdx.x;
    const float* xr = xn + (size_t)row * DIMX;
    float acc[24];
#pragma unroll
    for (int m = 0; m < 24; m++) acc[m] = 0.f;
    for (int i = threadIdx.x; i < DIMX; i += 256) {
        float v = xr[i];
#pragma unroll
        for (int r = 0; r < 8; r++) {
            acc[r]      += v * aq[i * 8 + r];
            acc[8 + r]  += v * ak[i * 8 + r];
            acc[16 + r] += v * av[i * 8 + r];
        }
    }
    __shared__ float sh[8][24];
    int wid = threadIdx.x >> 5, lane = threadIdx.x & 31;
#pragma unroll
    for (int m = 0; m < 24; m++)
        for (int o = 16; o > 0; o >>= 1)
            acc[m] += __shfl_xor_sync(0xffffffff, acc[m], o);
    if (lane == 0)
#pragma unroll
        for (int m = 0; m < 24; m++) sh[wid][m] = acc[m];
    __syncthreads();
    if (threadIdx.x < 24) {
        float s = 0.f;
        for (int w = 0; w < 8; w++) s += sh[w][threadIdx.x];
        xa[row * 24 + threadIdx.x] = s;
    }
}

// ---------------- qkv prep ----------------
__global__ void qkv_prep(const float* __restrict__ F, const float* __restrict__ XA,
                         const float* __restrict__ bq, const float* __restrict__ bk,
                         const float* __restrict__ bv,
                         float* __restrict__ Q, float* __restrict__ Kv, float* __restrict__ V) {
    int row = blockIdx.x;
    int n = row % NSEQ;
    __shared__ float qs[AINNER];
    __shared__ float ks[DHEAD];
    const float* Fr = F + (size_t)row * FPAD;
    const float* xa = XA + row * 24;
    float lq[8], lk[8], lv[8];
#pragma unroll
    for (int r = 0; r < 8; r++) { lq[r] = xa[r]; lk[r] = xa[8 + r]; lv[r] = xa[16 + r]; }

    for (int c = threadIdx.x; c < AINNER; c += 256) {
        float v = Fr[c];
#pragma unroll
        for (int r = 0; r < 8; r++) v += lq[r] * bq[r * AINNER + c];
        qs[c] = v;
    }
    if (threadIdx.x < DHEAD) {
        int c = threadIdx.x;
        float v = Fr[I0 + c];
#pragma unroll
        for (int r = 0; r < 8; r++) v += lk[r] * bk[r * DHEAD + c];
        ks[c] = v;
        float vv = Fr[I1 + c];
#pragma unroll
        for (int r = 0; r < 8; r++) vv += lv[r] * bv[r * DHEAD + c];
        V[(size_t)row * DHEAD + c] = vv;
    }
    __syncthreads();

    const float ln10k_inv32 = 9.2103403719761836f / 32.f;
    const float scale = 0.125f;
    for (int c = threadIdx.x; c < AINNER; c += 256) {
        int h = c >> 6, d = c & 63;
        int fi = d & 31;
        float freq = (float)n * __expf(-(float)fi * ln10k_inv32);
        float cs = cosf(freq), sn = sinf(freq);
        float me = qs[c];
        float partner = (d < 32) ? -qs[h * 64 + d + 32] : qs[h * 64 + d - 32];
        Q[(size_t)row * AINNER + c] = (me * cs + partner * sn) * scale;
    }
    if (threadIdx.x < DHEAD) {
        int d = threadIdx.x;
        int fi = d & 31;
        float freq = (float)n * __expf(-(float)fi * ln10k_inv32);
        float cs = cosf(freq), sn = sinf(freq);
        float me = ks[d];
        float partner = (d < 32) ? -ks[d + 32] : ks[d - 32];
        Kv[(size_t)row * DHEAD + d] = me * cs + partner * sn;
    }
}

// ---------------- causal flash attention (vectorized LDS) ----------------
__global__ __launch_bounds__(512) void attn_kernel(const float* __restrict__ Q,
                                                   const float* __restrict__ Kk,
                                                   const float* __restrict__ V,
                                                   float* __restrict__ O) {
    int row = blockIdx.x;
    int n = row % NSEQ;
    int b = row / NSEQ;
    int wid = threadIdx.x >> 5;
    int lane = threadIdx.x & 31;

    __shared__ float Qs[HEADS][64];
    __shared__ float Ks[32][68];
    __shared__ float Vs[32][68];   // 68: keeps float4 row starts 16B-aligned (R3 fix)
    __shared__ float Ps[HEADS][32];

    for (int idx = threadIdx.x; idx < HEADS * DHEAD; idx += 512)
        Qs[idx >> 6][idx & 63] = Q[(size_t)row * AINNER + idx];

    const float* Kb = Kk + (size_t)b * NSEQ * DHEAD;
    const float* Vb = V + (size_t)b * NSEQ * DHEAD;

    float m = -FLT_MAX, l = 0.f, acc0 = 0.f, acc1 = 0.f;

    for (int j0 = 0; j0 <= n; j0 += 32) {
        int cnt = min(32, n + 1 - j0);
        __syncthreads();
        {   // 512 threads load 32 rows x 16 float4
            int jj = threadIdx.x >> 4, d4 = (threadIdx.x & 15) * 4;
            float4 kv = make_float4(0, 0, 0, 0), vv = make_float4(0, 0, 0, 0);
            if (jj < cnt) {
                kv = *(const float4*)(Kb + (size_t)(j0 + jj) * DHEAD + d4);
                vv = *(const float4*)(Vb + (size_t)(j0 + jj) * DHEAD + d4);
            }
            *(float4*)&Ks[jj][d4] = kv;
            *(float4*)&Vs[jj][d4] = vv;
        }
        __syncthreads();

        float s = 0.f;
        {
            const float4* q4 = (const float4*)Qs[wid];
            const float4* k4 = (const float4*)Ks[lane];
#pragma unroll
            for (int d4 = 0; d4 < 16; d4++) {
                float4 qa = q4[d4], kb = k4[d4];
                s += qa.x * kb.x + qa.y * kb.y + qa.z * kb.z + qa.w * kb.w;
            }
        }
        if (lane >= cnt) s = -FLT_MAX;
        float smax = s;
        for (int o = 16; o > 0; o >>= 1) smax = fmaxf(smax, __shfl_xor_sync(0xffffffff, smax, o));
        float mnew = fmaxf(m, smax);
        float p = (lane < cnt) ? __expf(s - mnew) : 0.f;
        float ps = p;
        for (int o = 16; o > 0; o >>= 1) ps += __shfl_xor_sync(0xffffffff, ps, o);
        float corr = __expf(m - mnew);
        l = l * corr + ps;
        acc0 *= corr; acc1 *= corr;
        Ps[wid][lane] = p;
        __syncwarp();
        const float4* p4 = (const float4*)Ps[wid];
#pragma unroll
        for (int j4 = 0; j4 < 8; j4++) {
            float4 pj = p4[j4];
            float2 v0 = *(const float2*)&Vs[j4 * 4 + 0][lane * 2];
            float2 v1 = *(const float2*)&Vs[j4 * 4 + 1][lane * 2];
            float2 v2 = *(const float2*)&Vs[j4 * 4 + 2][lane * 2];
            float2 v3 = *(const float2*)&Vs[j4 * 4 + 3][lane * 2];
            acc0 += pj.x * v0.x + pj.y * v1.x + pj.z * v2.x + pj.w * v3.x;
            acc1 += pj.x * v0.y + pj.y * v1.y + pj.z * v2.y + pj.w * v3.y;
        }
        m = mnew;
    }
    float invl = 1.f / l;
    float2 o2 = make_float2(tf32r(acc0 * invl), tf32r(acc1 * invl));
    *(float2*)(O + (size_t)row * AINNER + wid * 64 + lane * 2) = o2;
}

// ---------------- OA[row,8] = OATTN_row @ a_o ----------------
__global__ void lora_oa_kernel(const float* __restrict__ oattn,
                               const float* __restrict__ ao,
                               float* __restrict__ oa) {
    int row = blockIdx.x;
    const float* xr = oattn + (size_t)row * AINNER;
    float acc[8];
#pragma unroll
    for (int r = 0; r < 8; r++) acc[r] = 0.f;
    for (int i = threadIdx.x; i < AINNER; i += 256) {
        float v = xr[i];
#pragma unroll
        for (int r = 0; r < 8; r++) acc[r] += v * ao[i * 8 + r];
    }
    __shared__ float sh[8][8];
    int wid = threadIdx.x >> 5, lane = threadIdx.x & 31;
#pragma unroll
    for (int r = 0; r < 8; r++)
        for (int o = 16; o > 0; o >>= 1)
            acc[r] += __shfl_xor_sync(0xffffffff, acc[r], o);
    if (lane == 0)
#pragma unroll
        for (int r = 0; r < 8; r++) sh[wid][r] = acc[r];
    __syncthreads();
    if (threadIdx.x < 8) {
        float s = 0.f;
        for (int w = 0; w < 8; w++) s += sh[w][threadIdx.x];
        oa[row * 8 + threadIdx.x] = s;
    }
}

// ---------------- H = tf32(silu(gate) * ff_x) ----------------
__global__ void hcombine(const float* __restrict__ F, float* __restrict__ H) {
    size_t idx = (size_t)blockIdx.x * blockDim.x + threadIdx.x;
    size_t row = idx / FFINNER;
    int c = (int)(idx % FFINNER);
    const float* Fr = F + row * FPAD;
    float g = Fr[I2 + FFINNER + c];
    float xx = Fr[I2 + c];
    H[idx] = tf32r(xx * g / (1.f + __expf(-g)));
}

// ---------------- out += OA @ b_o ----------------
__global__ void lora_o_add(const float* __restrict__ oa, const float* __restrict__ bo,
                           float* __restrict__ out) {
    int row = blockIdx.y;
    int c = blockIdx.x * 256 + threadIdx.x;
    float s = 0.f;
#pragma unroll
    for (int r = 0; r < 8; r++) s += oa[row * 8 + r] * bo[r * DIMX + c];
    out[(size_t)row * DIMX + c] += s;
}

// ---------------- launch ----------------
extern "C" void kernel_launch(void* const* d_in, const int* in_sizes, int n_in,
                              void* d_out, int out_size) {
    const float* x          = (const float*)d_in[0];
    const float* gamma      = (const float*)d_in[1];
    const float* w_fused    = (const float*)d_in[2];
    const float* w_attn_out = (const float*)d_in[3];
    const float* w_ff_out   = (const float*)d_in[4];
    const float* a_q        = (const float*)d_in[5];
    const float* b_q        = (const float*)d_in[6];
    const float* a_k        = (const float*)d_in[7];
    const float* b_k        = (const float*)d_in[8];
    const float* a_v        = (const float*)d_in[9];
    const float* b_v        = (const float*)d_in[10];
    const float* a_o        = (const float*)d_in[11];
    const float* b_o        = (const float*)d_in[12];
    float* out = (float*)d_out;

    float *XN, *WF, *F, *XA, *Q, *K, *V, *OATTN, *WAO, *H, *WFF, *OA;
    cudaGetSymbolAddress((void**)&XN, g_XN);
    cudaGetSymbolAddress((void**)&WF, g_WF);
    cudaGetSymbolAddress((void**)&F, g_F);
    cudaGetSymbolAddress((void**)&XA, g_XA);
    cudaGetSymbolAddress((void**)&Q, g_Q);
    cudaGetSymbolAddress((void**)&K, g_K);
    cudaGetSymbolAddress((void**)&V, g_V);
    cudaGetSymbolAddress((void**)&OATTN, g_OATTN);
    cudaGetSymbolAddress((void**)&WAO, g_WAO);
    cudaGetSymbolAddress((void**)&H, g_H);
    cudaGetSymbolAddress((void**)&WFF, g_WFF);
    cudaGetSymbolAddress((void**)&OA, g_OA);

    cudaFuncSetAttribute(tf32_gemm, cudaFuncAttributeMaxDynamicSharedMemorySize, GSMEM);

    // weight rounding (+pad for fused)
    round_pad<<<dim3((FPAD / 4 + 255) / 256, DIMX), 256>>>(w_fused, WF, FUSEDC / 4, FPAD / 4);
    round_pad<<<dim3((DIMX / 4 + 255) / 256, AINNER), 256>>>(w_attn_out, WAO, DIMX / 4, DIMX / 4);
    round_pad<<<dim3((DIMX / 4 + 255) / 256, FFINNER), 256>>>(w_ff_out, WFF, DIMX / 4, DIMX / 4);

    ln_kernel<<<ROWS, 256>>>(x, gamma, XN);
    tf32_gemm<<<dim3(ROWS / 128, FPAD / 128), 256, GSMEM>>>(XN, WF, F, FPAD, DIMX, 0);
    lora_xa_kernel<<<ROWS, 256>>>(XN, a_q, a_k, a_v, XA);
    qkv_prep<<<ROWS, 256>>>(F, XA, b_q, b_k, b_v, Q, K, V);
    attn_kernel<<<ROWS, 512>>>(Q, K, V, OATTN);
    tf32_gemm<<<dim3(ROWS / 128, DIMX / 128), 256, GSMEM>>>(OATTN, WAO, out, DIMX, AINNER, 0);
    lora_oa_kernel<<<ROWS, 256>>>(OATTN, a_o, OA);
    hcombine<<<(ROWS * (size_t)FFINNER) / 256, 256>>>(F, H);
    tf32_gemm<<<dim3(ROWS / 128, DIMX / 128), 256, GSMEM>>>(H, WFF, out, DIMX, FFINNER, 1);
    lora_o_add<<<dim3(DIMX / 256, ROWS), 256>>>(OA, b_o, out);
}